// round 9
// baseline (speedup 1.0000x reference)
#include <cuda_runtime.h>
#include <cuda_fp16.h>

#define S 160
#define SS (S*S)
#define S3 (S*S*S)
#define DG 96
#define DG2 (DG*DG)
#define DG3 (DG*DG*DG)
#define IMG_H 240
#define IMG_W 320
#define NVIEW 3
#define NSTEP 64
#define CLAMP_HI 158.999f          // f32(160 - 1.001)
#define NBLK 450                   // march blocks (10 x 15 x 3)

// packed resized SDF, half precision:
//   g_sdfh[(x*S+y)*S+z] = float2 whose bits are two __half2:
//     .x bits = (S[y][z], S[y][z+1])   .y bits = (S[y+1][z], S[y+1][z+1])
__device__ float2 g_sdfh[S3];      // 32 MB
__device__ float  g_psum[NBLK];
__device__ int    g_pcnt[NBLK];
__device__ int    g_count;         // zero-initialized; reset after use

union HF { __half2 h; float f; };

// ---------------------------------------------------------------------------
// Kernel 1: separable SDF resize 96^3 -> 160^3 (minus TRUNC), packed half4.
// ---------------------------------------------------------------------------
__global__ __launch_bounds__(192) void resize_sdf_kernel(const float* __restrict__ sdf) {
    int b = blockIdx.x;            // S*S
    int i = b / S, j = b % S;
    int t = threadIdx.x;           // 192

    float cx = (i * 95.0f) / 159.0f;
    int x0 = (int)cx; float fx = cx - (float)x0; int x1 = min(x0 + 1, DG - 1);

    __shared__ float ls[2][96];

    {
        int row = t >= 96;                       // 0 -> j, 1 -> j+1
        int z = t - row * 96;                    // 0..95
        int jj = row ? min(j + 1, S - 1) : j;
        float cy = (jj * 95.0f) / 159.0f;
        int y0 = (int)cy; float fy = cy - (float)y0; int y1 = min(y0 + 1, DG - 1);
        int base = (x0 * DG + y0) * DG + z;
        int xs = (x1 - x0) * DG2;
        int ys = (y1 - y0) * DG;
        float gxf = 1.0f - fx, gyf = 1.0f - fy;
        ls[row][z] = __ldg(sdf + base) * (gxf * gyf) + __ldg(sdf + base + ys) * (gxf * fy)
                   + __ldg(sdf + base + xs) * (fx * gyf) + __ldg(sdf + base + xs + ys) * (fx * fy);
    }
    __syncthreads();

    if (t < S) {
        float czf = (t * 95.0f) / 159.0f;
        int z0 = (int)czf; float fz = czf - (float)z0; int z1 = min(z0 + 1, DG - 1);
        float vA0 = fmaf(fz, ls[0][z1] - ls[0][z0], ls[0][z0]) - 1.5f;
        float vB0 = fmaf(fz, ls[1][z1] - ls[1][z0], ls[1][z0]) - 1.5f;

        int t1 = min(t + 1, S - 1);
        float czg = (t1 * 95.0f) / 159.0f;
        int w0 = (int)czg; float fw = czg - (float)w0; int w1 = min(w0 + 1, DG - 1);
        float vA1 = fmaf(fw, ls[0][w1] - ls[0][w0], ls[0][w0]) - 1.5f;
        float vB1 = fmaf(fw, ls[1][w1] - ls[1][w0], ls[1][w0]) - 1.5f;

        HF lo, hi;
        lo.h = __floats2half2_rn(vA0, vA1);
        hi.h = __floats2half2_rn(vB0, vB1);
        g_sdfh[(i * S + j) * S + t] = make_float2(lo.f, hi.f);
    }
}

// ---------------------------------------------------------------------------
// half4 SDF sample: 2x 8B loads, fp32 lerp
// ---------------------------------------------------------------------------
__device__ __forceinline__ float sdf_sample_h(int x0, int y0, int z0,
                                              float fx, float fy, float fz) {
    const float2* p = g_sdfh + ((x0 * S + y0) * S + z0);
    float2 A = __ldg(p);
    float2 B = __ldg(p + SS);
    HF u;
    u.f = A.x; float2 al = __half22float2(u.h);
    u.f = A.y; float2 ah = __half22float2(u.h);
    u.f = B.x; float2 bl = __half22float2(u.h);
    u.f = B.y; float2 bh = __half22float2(u.h);
    float a0 = fmaf(fz, al.y - al.x, al.x);
    float a1 = fmaf(fz, ah.y - ah.x, ah.x);
    float b0 = fmaf(fz, bl.y - bl.x, bl.x);
    float b1 = fmaf(fz, bh.y - bh.x, bh.x);
    float va = fmaf(fy, a1 - a0, a0);
    float vb = fmaf(fy, b1 - b0, b0);
    return fmaf(fx, vb - va, va);
}

// 3-level separable weights for resized-trilerp-of-source-trilerp along one axis
__device__ __forceinline__ void axis_w(int c0, float f, float* W, int* g) {
    float cc0 = (c0 * 95.0f) / 159.0f;
    int b0 = (int)cc0; float f0 = cc0 - (float)b0;
    float cc1 = ((c0 + 1) * 95.0f) / 159.0f;
    int b1 = (int)cc1; float f1 = cc1 - (float)b1;
    int l = b1 - b0;                    // 0 or 1
    float g0 = 1.0f - f;
    float wa = f * (1.0f - f1), wb = f * f1;
    W[0] = g0 * (1.0f - f0) + (l == 0 ? wa : 0.0f);
    W[1] = g0 * f0 + (l == 0 ? wb : wa);
    W[2] = (l == 0 ? 0.0f : wb);
    g[0] = b0;
    g[1] = min(b0 + 1, DG - 1);
    g[2] = min(b0 + 2, DG - 1);
}

__device__ __forceinline__ float gather27(const float* __restrict__ src,
                                          const int* gx, const int* gy, const int* gz,
                                          const float* Wx, const float* Wy, const float* Wz) {
    float acc = 0.0f;
#pragma unroll
    for (int ia = 0; ia < 3; ia++) {
        float accy = 0.0f;
#pragma unroll
        for (int ib = 0; ib < 3; ib++) {
            const float* rr = src + (gx[ia] * DG + gy[ib]) * DG;
            float accz = __ldg(rr + gz[0]) * Wz[0]
                       + __ldg(rr + gz[1]) * Wz[1]
                       + __ldg(rr + gz[2]) * Wz[2];
            accy = fmaf(Wy[ib], accz, accy);
        }
        acc = fmaf(Wx[ia], accy, acc);
    }
    return acc;
}

// shade one finished ray -> (contrib, cnt)
__device__ __forceinline__ void shade_ray(float t, float ox, float oy, float oz,
                                          float dx, float dy, float dz,
                                          const float* __restrict__ rgb,
                                          const float* __restrict__ sem,
                                          const float* __restrict__ views,
                                          int v, int w, int h,
                                          float& contrib, int& cnt) {
    float px = fmaf(t, dx, ox);
    float py = fmaf(t, dy, oy);
    float pz = fmaf(t, dz, oz);
    float cx = fminf(fmaxf(px, 0.0f), CLAMP_HI);
    float cy = fminf(fmaxf(py, 0.0f), CLAMP_HI);
    float cz = fminf(fmaxf(pz, 0.0f), CLAMP_HI);
    int x0 = (int)cx, y0 = (int)cy, z0 = (int)cz;
    float fx = cx - (float)x0, fy = cy - (float)y0, fz = cz - (float)z0;

    float s = sdf_sample_h(x0, y0, z0, fx, fy, fz);

    bool inside = (px >= 0.0f) && (px <= 159.0f)
               && (py >= 0.0f) && (py <= 159.0f)
               && (pz >= 0.0f) && (pz <= 159.0f);
    if (!(inside && (fabsf(s) < 1.0f))) { contrib = 0.0f; cnt = 0; return; }

    float Wx[3], Wy[3], Wz[3];
    int gx[3], gy[3], gz[3];
    axis_w(x0, fx, Wx, gx);
    axis_w(y0, fy, Wy, gy);
    axis_w(z0, fz, Wz, gz);

    float c0 = gather27(rgb,           gx, gy, gz, Wx, Wy, Wz);
    float c1 = gather27(rgb + DG3,     gx, gy, gz, Wx, Wy, Wz);
    float c2 = gather27(rgb + 2 * DG3, gx, gy, gz, Wx, Wy, Wz);

    int nx0 = min((int)(x0 * 0.6f), DG - 1);
    int nx1 = min((int)((x0 + 1) * 0.6f), DG - 1);
    int ny0 = min((int)(y0 * 0.6f), DG - 1);
    int ny1 = min((int)((y0 + 1) * 0.6f), DG - 1);
    int nz0 = min((int)(z0 * 0.6f), DG - 1);
    int nz1 = min((int)((z0 + 1) * 0.6f), DG - 1);
    float gxf = 1.0f - fx, gyf = 1.0f - fy, gzf = 1.0f - fz;
    const float* s00 = sem + (nx0 * DG + ny0) * DG;
    const float* s01 = sem + (nx0 * DG + ny1) * DG;
    const float* s10 = sem + (nx1 * DG + ny0) * DG;
    const float* s11 = sem + (nx1 * DG + ny1) * DG;
    float wv = gxf * gyf * (gzf * __ldg(s00 + nz0) + fz * __ldg(s00 + nz1))
             + gxf * fy  * (gzf * __ldg(s01 + nz0) + fz * __ldg(s01 + nz1))
             + fx  * gyf * (gzf * __ldg(s10 + nz0) + fz * __ldg(s10 + nz1))
             + fx  * fy  * (gzf * __ldg(s11 + nz0) + fz * __ldg(s11 + nz1));

    const float* vw = views + ((size_t)(v * IMG_H + h) * IMG_W + w) * 3;
    contrib = (fabsf(c0 - vw[0]) + fabsf(c1 - vw[1]) + fabsf(c2 - vw[2])) * wv;
    cnt = 1;
}

// ---------------------------------------------------------------------------
// Kernel 2: fused march (2 rays/thread) + shade + loss.
// grid (10, 15, 3), block 256. Warp tile 8x4; rays at h and h+4 (8x8/warp).
// ---------------------------------------------------------------------------
__global__ __launch_bounds__(256) void march_kernel(
        const float* __restrict__ rgb,
        const float* __restrict__ sem,
        const float* __restrict__ poses,
        const float* __restrict__ views,
        float* __restrict__ out) {
    int tid = threadIdx.x;
    int warp = tid >> 5, lane = tid & 31;
    int wx = warp & 3, wy = warp >> 2;          // wy in 0..1
    int lx = lane & 7, ly = lane >> 3;
    int w  = blockIdx.x * 32 + wx * 8 + lx;
    int hA = blockIdx.y * 16 + wy * 8 + ly;     // rays A: rows 0-3 of warp tile
    int hB = hA + 4;                            // rays B: rows 4-7
    int v  = blockIdx.z;

    const float offx[3] = {0.0f, 36.0f, 40.0f};
    const float offz[3] = {0.0f, 44.0f, 23.0f};
    const float* M = poses + v * 16;
    float ox = M[3]  / 0.0301f + offx[v];
    float oy = M[7]  / 0.0301f;
    float oz = M[11] / 0.0301f + offz[v];
    float uu = ((float)w - 160.0f) / 277.0f;

    float vvA = ((float)hA - 120.0f) / 277.0f;
    float dxA = M[0] * uu + M[1] * vvA + M[2];
    float dyA = M[4] * uu + M[5] * vvA + M[6];
    float dzA = M[8] * uu + M[9] * vvA + M[10];
    float nA = sqrtf(dxA * dxA + dyA * dyA + dzA * dzA);
    dxA /= nA; dyA /= nA; dzA /= nA;

    float vvB = ((float)hB - 120.0f) / 277.0f;
    float dxB = M[0] * uu + M[1] * vvB + M[2];
    float dyB = M[4] * uu + M[5] * vvB + M[6];
    float dzB = M[8] * uu + M[9] * vvB + M[10];
    float nB = sqrtf(dxB * dxB + dyB * dyB + dzB * dzB);
    dxB /= nB; dyB /= nB; dzB /= nB;

    float tA = 0.0f, tB = 0.0f;
    bool aliveA = true, aliveB = true;
#pragma unroll 1
    for (int it = 0; it < NSTEP; ++it) {
        // --- issue both loads first (independent chains) ---
        float2 A0, A1, B0, B1;
        float fxA, fyA, fzA, fxB, fyB, fzB;
        bool doA = aliveA, doB = aliveB;

        float pxA = fmaf(tA, dxA, ox), pyA = fmaf(tA, dyA, oy), pzA = fmaf(tA, dzA, oz);
        if (doA) {
            bool dead = (pxA < 0.0f && dxA <= 0.0f) || (pxA > 159.0f && dxA >= 0.0f)
                     || (pyA < 0.0f && dyA <= 0.0f) || (pyA > 159.0f && dyA >= 0.0f)
                     || (pzA < 0.0f && dzA <= 0.0f) || (pzA > 159.0f && dzA >= 0.0f);
            if (dead) { aliveA = false; doA = false; }
        }
        float pxB = fmaf(tB, dxB, ox), pyB = fmaf(tB, dyB, oy), pzB = fmaf(tB, dzB, oz);
        if (doB) {
            bool dead = (pxB < 0.0f && dxB <= 0.0f) || (pxB > 159.0f && dxB >= 0.0f)
                     || (pyB < 0.0f && dyB <= 0.0f) || (pyB > 159.0f && dyB >= 0.0f)
                     || (pzB < 0.0f && dzB <= 0.0f) || (pzB > 159.0f && dzB >= 0.0f);
            if (dead) { aliveB = false; doB = false; }
        }

        if (doA) {
            float cx = fminf(fmaxf(pxA, 0.0f), CLAMP_HI);
            float cy = fminf(fmaxf(pyA, 0.0f), CLAMP_HI);
            float cz = fminf(fmaxf(pzA, 0.0f), CLAMP_HI);
            int x0 = (int)cx, y0 = (int)cy, z0 = (int)cz;
            fxA = cx - (float)x0; fyA = cy - (float)y0; fzA = cz - (float)z0;
            const float2* p = g_sdfh + ((x0 * S + y0) * S + z0);
            A0 = __ldg(p); A1 = __ldg(p + SS);
        }
        if (doB) {
            float cx = fminf(fmaxf(pxB, 0.0f), CLAMP_HI);
            float cy = fminf(fmaxf(pyB, 0.0f), CLAMP_HI);
            float cz = fminf(fmaxf(pzB, 0.0f), CLAMP_HI);
            int x0 = (int)cx, y0 = (int)cy, z0 = (int)cz;
            fxB = cx - (float)x0; fyB = cy - (float)y0; fzB = cz - (float)z0;
            const float2* p = g_sdfh + ((x0 * S + y0) * S + z0);
            B0 = __ldg(p); B1 = __ldg(p + SS);
        }

        // --- consume ---
        if (doA) {
            HF u;
            u.f = A0.x; float2 al = __half22float2(u.h);
            u.f = A0.y; float2 ah = __half22float2(u.h);
            u.f = A1.x; float2 bl = __half22float2(u.h);
            u.f = A1.y; float2 bh = __half22float2(u.h);
            float a0 = fmaf(fzA, al.y - al.x, al.x);
            float a1 = fmaf(fzA, ah.y - ah.x, ah.x);
            float b0 = fmaf(fzA, bl.y - bl.x, bl.x);
            float b1 = fmaf(fzA, bh.y - bh.x, bh.x);
            float va = fmaf(fyA, a1 - a0, a0);
            float vb = fmaf(fyA, b1 - b0, b0);
            float s = fmaf(fxA, vb - va, va);
            tA = fmaf(fmaxf(s, 0.25f), 2.0f, tA);
        }
        if (doB) {
            HF u;
            u.f = B0.x; float2 al = __half22float2(u.h);
            u.f = B0.y; float2 ah = __half22float2(u.h);
            u.f = B1.x; float2 bl = __half22float2(u.h);
            u.f = B1.y; float2 bh = __half22float2(u.h);
            float a0 = fmaf(fzB, al.y - al.x, al.x);
            float a1 = fmaf(fzB, ah.y - ah.x, ah.x);
            float b0 = fmaf(fzB, bl.y - bl.x, bl.x);
            float b1 = fmaf(fzB, bh.y - bh.x, bh.x);
            float va = fmaf(fyB, a1 - a0, a0);
            float vb = fmaf(fyB, b1 - b0, b0);
            float s = fmaf(fxB, vb - va, va);
            tB = fmaf(fmaxf(s, 0.25f), 2.0f, tB);
        }

        if (__all_sync(0xffffffffu, !aliveA && !aliveB)) break;
    }

    float contrib = 0.0f;
    int cnt = 0;
    if (aliveA) {
        float c; int n;
        shade_ray(tA, ox, oy, oz, dxA, dyA, dzA, rgb, sem, views, v, w, hA, c, n);
        contrib += c; cnt += n;
    }
    if (aliveB) {
        float c; int n;
        shade_ray(tB, ox, oy, oz, dxB, dyB, dzB, rgb, sem, views, v, w, hB, c, n);
        contrib += c; cnt += n;
    }

    // deterministic block reduction + last-block finish
    __shared__ float ssum[256];
    __shared__ int scnt[256];
    ssum[tid] = contrib;
    scnt[tid] = cnt;
    __syncthreads();
#pragma unroll
    for (int o = 128; o > 0; o >>= 1) {
        if (tid < o) {
            ssum[tid] += ssum[tid + o];
            scnt[tid] += scnt[tid + o];
        }
        __syncthreads();
    }
    int bid = (blockIdx.z * gridDim.y + blockIdx.y) * gridDim.x + blockIdx.x;
    __shared__ bool amLast;
    if (tid == 0) {
        g_psum[bid] = ssum[0];
        g_pcnt[bid] = scnt[0];
        __threadfence();
        int tk = atomicAdd(&g_count, 1);
        amLast = (tk == NBLK - 1);
    }
    __syncthreads();

    if (amLast) {
        float sacc = 0.0f; int cacc = 0;
        for (int k = tid; k < NBLK; k += 256) {
            sacc += g_psum[k];
            cacc += g_pcnt[k];
        }
        ssum[tid] = sacc;
        scnt[tid] = cacc;
        __syncthreads();
#pragma unroll
        for (int o = 128; o > 0; o >>= 1) {
            if (tid < o) {
                ssum[tid] += ssum[tid + o];
                scnt[tid] += scnt[tid + o];
            }
            __syncthreads();
        }
        if (tid == 0) {
            float nv = 3.0f * (float)scnt[0];
            out[0] = 8.0f * ssum[0] / fmaxf(nv, 1.0f);
            g_count = 0;
        }
    }
}

// ---------------------------------------------------------------------------
extern "C" void kernel_launch(void* const* d_in, const int* in_sizes, int n_in,
                              void* d_out, int out_size) {
    const float* sdf   = (const float*)d_in[0];
    const float* rgb   = (const float*)d_in[1];
    const float* sem   = (const float*)d_in[2];
    const float* poses = (const float*)d_in[3];
    const float* views = (const float*)d_in[4];

    resize_sdf_kernel<<<S * S, 192>>>(sdf);
    dim3 mg(IMG_W / 32, IMG_H / 16, NVIEW);
    march_kernel<<<mg, 256>>>(rgb, sem, poses, views, (float*)d_out);
}